// round 5
// baseline (speedup 1.0000x reference)
#include <cuda_runtime.h>
#include <cuda_bf16.h>
#include <cstdint>
#include <math.h>

// ---------------------------------------------------------------------------
// Problem constants
#define T_TOK 4096
#define H_DIM 1024
#define I_DIM 2048
#define N_EXP 8
#define K_TOP 2
#define MAXROWS 10240   // 8192 pairs + per-expert padding to 128 => 80 tiles

// GEMM tiling
#define BM 128
#define BN 128
#define BK 32
#define ROWB 80                      // padded smem row: 32 bf16 (64B) + 16B pad
#define TILE_BYTES (128 * ROWB)      // 10240
#define STAGE_BYTES (4 * TILE_BYTES) // Ahi, Alo, Bhi, Blo
#define N_STAGE 3
#define SMEM_TOTAL (N_STAGE * STAGE_BYTES) // 122880

// ---------------------------------------------------------------------------
// Scratch (device globals — allocation-free; referenced ONLY from device code)
__device__ int   d_count[N_EXP];
__device__ int   d_cursor[N_EXP];
__device__ int   d_seg[N_EXP + 1];
__device__ int   d_tok[MAXROWS];
__device__ int   d_pairrow[T_TOK * K_TOP];
__device__ float d_topw[T_TOK * K_TOP];
__device__ int   d_tope[T_TOK * K_TOP];

__device__ unsigned short d_xhi[(size_t)T_TOK * H_DIM];
__device__ unsigned short d_xlo[(size_t)T_TOK * H_DIM];
// W1 = gate/up interleaved at 8-col granularity: [E][4096][1024]
//   gate col j -> n' = (j>>3)*16 + (j&7);  up col j -> n' = (j>>3)*16 + 8 + (j&7)
__device__ unsigned short d_W1hi[(size_t)N_EXP * 2 * I_DIM * H_DIM];
__device__ unsigned short d_W1lo[(size_t)N_EXP * 2 * I_DIM * H_DIM];
// Wd transposed: [E][1024][2048]
__device__ unsigned short d_Wdhi[(size_t)N_EXP * H_DIM * I_DIM];
__device__ unsigned short d_Wdlo[(size_t)N_EXP * H_DIM * I_DIM];
__device__ unsigned short d_midhi[(size_t)MAXROWS * I_DIM];
__device__ unsigned short d_midlo[(size_t)MAXROWS * I_DIM];
__device__ float d_eo[(size_t)MAXROWS * H_DIM];

// ---------------------------------------------------------------------------
// PTX macros (baseline PTX only: compiles for compute_103 target)
#define CP16(dst, src, sz) \
    asm volatile("cp.async.cg.shared.global [%0], [%1], 16, %2;" \
                 :: "r"(dst), "l"(src), "r"(sz) : "memory")
#define CP_COMMIT() asm volatile("cp.async.commit_group;" ::: "memory")
#define CP_WAIT1()  asm volatile("cp.async.wait_group 1;" ::: "memory")

#define LDSM_X4(r, addr) \
    asm volatile("ldmatrix.sync.aligned.m8n8.x4.shared.b16 {%0,%1,%2,%3}, [%4];" \
                 : "=r"((r)[0]), "=r"((r)[1]), "=r"((r)[2]), "=r"((r)[3]) : "r"(addr))

#define MMA_BF16(c, a, b) \
    asm volatile("mma.sync.aligned.m16n8k16.row.col.f32.bf16.bf16.f32 " \
                 "{%0,%1,%2,%3}, {%4,%5,%6,%7}, {%8,%9}, {%0,%1,%2,%3};" \
                 : "+f"((c)[0]), "+f"((c)[1]), "+f"((c)[2]), "+f"((c)[3]) \
                 : "r"((a)[0]), "r"((a)[1]), "r"((a)[2]), "r"((a)[3]), \
                   "r"((b)[0]), "r"((b)[1]))

// bf16 split helpers
__device__ __forceinline__ unsigned short bfbits(float v) {
    __nv_bfloat16 b = __float2bfloat16_rn(v);
    return *reinterpret_cast<unsigned short*>(&b);
}
__device__ __forceinline__ float bfval(unsigned short u) {
    __nv_bfloat16 b;
    *reinterpret_cast<unsigned short*>(&b) = u;
    return __bfloat162float(b);
}
__device__ __forceinline__ void split2(float v, unsigned short& h, unsigned short& l) {
    h = bfbits(v);
    l = bfbits(v - bfval(h));
}
__device__ __forceinline__ float silu_mul(float g, float u) {
    return g / (1.f + expf(-g)) * u;
}

// ---------------------------------------------------------------------------
__global__ void init_kernel() {
    int tid = threadIdx.x;
    if (tid < N_EXP) { d_count[tid] = 0; d_cursor[tid] = 0; }
    for (int i = tid; i < MAXROWS; i += blockDim.x) d_tok[i] = -1;
}

// fp32 x -> bf16 hi/lo
__global__ void convx_kernel(const float* __restrict__ x) {
    size_t i = (size_t)blockIdx.x * 256 + threadIdx.x;  // float4 index
    float4 v = ((const float4*)x)[i];
    ushort4 h, l;
    split2(v.x, h.x, l.x); split2(v.y, h.y, l.y);
    split2(v.z, h.z, l.z); split2(v.w, h.w, l.w);
    ((ushort4*)d_xhi)[i] = h;
    ((ushort4*)d_xlo)[i] = l;
}

// transpose + hi/lo split with vectorized writes.
// mode 0: Wg -> W1 (interleaved even groups); 1: Wu -> W1 (odd); 2: Wd.
// Block: 64 k x 32 n tile, 256 threads.
__global__ void wtrans_kernel(const float* __restrict__ W, int mode) {
    __shared__ float tile[64][33];
    const int Kd = (mode == 2) ? I_DIM : H_DIM;
    const int Nd = (mode == 2) ? H_DIM : I_DIM;
    const int Nb = (mode == 2) ? H_DIM : 2 * I_DIM;
    unsigned short* Thi = (mode == 2) ? d_Wdhi : d_W1hi;
    unsigned short* Tlo = (mode == 2) ? d_Wdlo : d_W1lo;

    int e = blockIdx.z;
    const float* We = W + (size_t)e * Kd * Nd;
    int nbase = blockIdx.x * 32, kbase = blockIdx.y * 64;
    int tid = threadIdx.x, tx = tid & 31, ty = tid >> 5;
#pragma unroll
    for (int r = 0; r < 64; r += 8)
        tile[r + ty][tx] = We[(size_t)(kbase + r + ty) * Nd + nbase + tx];
    __syncthreads();

    size_t ebase = (size_t)e * Nb * Kd;
#pragma unroll
    for (int task = tid; task < 512; task += 256) {
        int n = task >> 4, q = task & 15;
        int j = nbase + n;
        int np = (mode == 2) ? j
                 : (((j >> 3) << 4) | (mode == 1 ? 8 : 0) | (j & 7));
        ushort4 h, l;
        split2(tile[q * 4 + 0][n], h.x, l.x);
        split2(tile[q * 4 + 1][n], h.y, l.y);
        split2(tile[q * 4 + 2][n], h.z, l.z);
        split2(tile[q * 4 + 3][n], h.w, l.w);
        size_t o = ebase + (size_t)np * Kd + kbase + q * 4;
        *(ushort4*)(Thi + o) = h;
        *(ushort4*)(Tlo + o) = l;
    }
}

// One warp per token: logits, softmax, top-2, expert counting.
__global__ void router_kernel(const float* __restrict__ x,
                              const float* __restrict__ gw,
                              float* __restrict__ out_logits) {
    int warp = threadIdx.x >> 5, lane = threadIdx.x & 31;
    int t = blockIdx.x * 8 + warp;
    if (t >= T_TOK) return;
    const float* xr = x + (size_t)t * H_DIM;
    float acc[N_EXP];
#pragma unroll
    for (int e = 0; e < N_EXP; e++) acc[e] = 0.f;
    for (int i = lane; i < H_DIM; i += 32) {
        float xv = xr[i];
        float4 a = __ldg((const float4*)(gw + (size_t)i * N_EXP));
        float4 b = __ldg((const float4*)(gw + (size_t)i * N_EXP) + 1);
        acc[0] += xv * a.x; acc[1] += xv * a.y; acc[2] += xv * a.z; acc[3] += xv * a.w;
        acc[4] += xv * b.x; acc[5] += xv * b.y; acc[6] += xv * b.z; acc[7] += xv * b.w;
    }
#pragma unroll
    for (int off = 16; off > 0; off >>= 1)
#pragma unroll
        for (int e = 0; e < N_EXP; e++)
            acc[e] += __shfl_xor_sync(0xffffffffu, acc[e], off);
    if (lane == 0) {
#pragma unroll
        for (int e = 0; e < N_EXP; e++) out_logits[(size_t)t * N_EXP + e] = acc[e];
        float m = acc[0];
#pragma unroll
        for (int e = 1; e < N_EXP; e++) m = fmaxf(m, acc[e]);
        float p[N_EXP], s = 0.f;
#pragma unroll
        for (int e = 0; e < N_EXP; e++) { p[e] = expf(acc[e] - m); s += p[e]; }
        float inv = 1.f / s;
        int i0 = 0; float b0 = p[0];
#pragma unroll
        for (int e = 1; e < N_EXP; e++) if (p[e] > b0) { b0 = p[e]; i0 = e; }
        int i1 = -1; float b1 = -1.f;
#pragma unroll
        for (int e = 0; e < N_EXP; e++) if (e != i0 && p[e] > b1) { b1 = p[e]; i1 = e; }
        d_tope[t * 2 + 0] = i0; d_topw[t * 2 + 0] = b0 * inv;
        d_tope[t * 2 + 1] = i1; d_topw[t * 2 + 1] = b1 * inv;
        atomicAdd(&d_count[i0], 1);
        atomicAdd(&d_count[i1], 1);
    }
}

__global__ void scan_kernel() {
    if (threadIdx.x == 0) {
        int off = 0;
#pragma unroll
        for (int e = 0; e < N_EXP; e++) { d_seg[e] = off; off += (d_count[e] + 127) & ~127; }
        d_seg[N_EXP] = off;
    }
}

__global__ void scatter_kernel() {
    int t = blockIdx.x * blockDim.x + threadIdx.x;
    if (t >= T_TOK) return;
#pragma unroll
    for (int k = 0; k < K_TOP; k++) {
        int e = d_tope[t * 2 + k];
        int pos = atomicAdd(&d_cursor[e], 1);
        int row = d_seg[e] + pos;
        d_tok[row] = t;
        d_pairrow[t * 2 + k] = row;
    }
}

// ---------------------------------------------------------------------------
// Grouped GEMM on mma.sync.m16n8k16 bf16, hi/lo split (3 passes), fp32 acc.
// MODE 0: A = gather(x) [K=1024], B = W1 (g/u interleaved), epilogue fuses
//         silu(g)*u -> bf16 hi/lo -> d_mid  (acc j even = gate, odd = up)
// MODE 1: A = mid [K=2048], B = Wd, C -> d_eo (fp32)
// 128x128x32 CTA tile, 8 warps of 64x32, 3-stage cp.async pipeline.
template <int MODE>
__global__ __launch_bounds__(256, 1)
void mma_gemm_kernel()
{
    constexpr int Kdim = (MODE == 0) ? H_DIM : I_DIM;
    constexpr int Nb   = (MODE == 0) ? 2 * I_DIM : H_DIM;

    extern __shared__ char sm[];
    int row0 = blockIdx.x * BM;
    if (row0 >= d_seg[N_EXP]) return;

    const unsigned short* __restrict__ Ahi_g = (MODE == 0) ? d_xhi : d_midhi;
    const unsigned short* __restrict__ Alo_g = (MODE == 0) ? d_xlo : d_midlo;
    const unsigned short* __restrict__ Bhi_g = (MODE == 0) ? d_W1hi : d_Wdhi;
    const unsigned short* __restrict__ Blo_g = (MODE == 0) ? d_W1lo : d_Wdlo;

    uint32_t sbase = (uint32_t)__cvta_generic_to_shared(sm);
    int tid = threadIdx.x, lane = tid & 31, wid = tid >> 5;
    int n0 = blockIdx.y * BN;

    int e = 0;
#pragma unroll
    for (int i = 0; i < N_EXP - 1; i++) if (row0 >= d_seg[i + 1]) e = i + 1;

    // ---- per-thread load setup: 2 rows per tile (r and r+64), 16B chunk kc
    int r1 = tid >> 2, kc = tid & 3;
    const unsigned short *pAh[2], *pAl[2], *pBh[2], *pBl[2];
    uint32_t szA[2], dstoff[2];
#pragma unroll
    for (int h2 = 0; h2 < 2; h2++) {
        int r = r1 + h2 * 64;
        dstoff[h2] = (uint32_t)(r * ROWB + kc * 16);
        if (MODE == 0) {
            int tok = d_tok[row0 + r];
            if (tok >= 0) {
                pAh[h2] = Ahi_g + (size_t)tok * Kdim + kc * 8;
                pAl[h2] = Alo_g + (size_t)tok * Kdim + kc * 8;
                szA[h2] = 16;
            } else {
                pAh[h2] = Ahi_g; pAl[h2] = Alo_g; szA[h2] = 0;  // zero-fill
            }
        } else {
            pAh[h2] = Ahi_g + (size_t)(row0 + r) * Kdim + kc * 8;
            pAl[h2] = Alo_g + (size_t)(row0 + r) * Kdim + kc * 8;
            szA[h2] = 16;
        }
        size_t bo = ((size_t)e * Nb + n0 + r) * Kdim + kc * 8;
        pBh[h2] = Bhi_g + bo;
        pBl[h2] = Blo_g + bo;
    }

#define LOAD_STAGE(s, kof) do { \
    uint32_t sb_ = sbase + (s) * STAGE_BYTES; \
    _Pragma("unroll") \
    for (int h2 = 0; h2 < 2; h2++) { \
        CP16(sb_ + 0 * TILE_BYTES + dstoff[h2], pAh[h2] + (kof), szA[h2]); \
        CP16(sb_ + 1 * TILE_BYTES + dstoff[h2], pAl[h2] + (kof), szA[h2]); \
        CP16(sb_ + 2 * TILE_BYTES + dstoff[h2], pBh[h2] + (kof), 16u); \
        CP16(sb_ + 3 * TILE_BYTES + dstoff[h2], pBl[h2] + (kof), 16u); \
    } \
} while (0)

    // ---- compute setup
    int wm = (wid & 1) * 64, wn = (wid >> 1) * 32;
    uint32_t a_off = (uint32_t)((wm + (lane & 15)) * ROWB + (lane >> 4) * 16);
    uint32_t b_off = (uint32_t)((wn + (lane & 7) + ((lane >> 4) << 3)) * ROWB +
                                ((lane >> 3) & 1) * 16);

    float acc[4][4][4];
#pragma unroll
    for (int i = 0; i < 4; i++)
#pragma unroll
        for (int j = 0; j < 4; j++)
#pragma unroll
            for (int q = 0; q < 4; q++) acc[i][j][q] = 0.f;

    const int nk = Kdim / BK;
    LOAD_STAGE(0, 0);
    CP_COMMIT();
    LOAD_STAGE(1, BK);
    CP_COMMIT();

    for (int ks = 0; ks < nk; ks++) {
        CP_WAIT1();          // stage ks resident (<=1 group pending)
        __syncthreads();     // all warps done with stage (ks-1): safe to refill

        int kpre = ks + 2;
        if (kpre < nk) {
            int sp = kpre - (kpre / N_STAGE) * N_STAGE;
            LOAD_STAGE(sp, kpre * BK);
        }
        CP_COMMIT();         // commit (possibly empty) keeps group accounting uniform

        uint32_t sb = sbase + (uint32_t)(ks - (ks / N_STAGE) * N_STAGE) * STAGE_BYTES;
#pragma unroll
        for (int h = 0; h < 2; h++) {  // two k16 steps per BK=32
            uint32_t ah[4][4], al[4][4], bh[4][2], bl[4][2];
#pragma unroll
            for (int i = 0; i < 4; i++) {
                uint32_t ad = sb + a_off + i * (16 * ROWB) + h * 32;
                LDSM_X4(ah[i], ad);
                LDSM_X4(al[i], ad + TILE_BYTES);
            }
#pragma unroll
            for (int jp = 0; jp < 2; jp++) {
                uint32_t tmp[4];
                uint32_t bd = sb + 2 * TILE_BYTES + b_off + jp * (16 * ROWB) + h * 32;
                LDSM_X4(tmp, bd);
                bh[jp * 2][0] = tmp[0]; bh[jp * 2][1] = tmp[1];
                bh[jp * 2 + 1][0] = tmp[2]; bh[jp * 2 + 1][1] = tmp[3];
                LDSM_X4(tmp, bd + TILE_BYTES);
                bl[jp * 2][0] = tmp[0]; bl[jp * 2][1] = tmp[1];
                bl[jp * 2 + 1][0] = tmp[2]; bl[jp * 2 + 1][1] = tmp[3];
            }
#pragma unroll
            for (int i = 0; i < 4; i++)
#pragma unroll
                for (int j = 0; j < 4; j++) {
                    MMA_BF16(acc[i][j], ah[i], bh[j]);
                    MMA_BF16(acc[i][j], ah[i], bl[j]);
                    MMA_BF16(acc[i][j], al[i], bh[j]);
                }
        }
    }

    // ---- epilogue
    int rin = lane >> 2, cin = (lane & 3) * 2;
    if (MODE == 0) {
        // acc[i][jp*2] = gate, acc[i][jp*2+1] = up for the SAME logical cols
        int midcol0 = ((n0 + wn) >> 4) << 3;   // logical mid col base for this warp
#pragma unroll
        for (int i = 0; i < 4; i++)
#pragma unroll
            for (int jp = 0; jp < 2; jp++) {
                const float* g = acc[i][jp * 2];
                const float* u = acc[i][jp * 2 + 1];
                int colb = midcol0 + jp * 8 + cin;
#pragma unroll
                for (int hf = 0; hf < 2; hf++) {
                    float m0 = silu_mul(g[hf * 2 + 0], u[hf * 2 + 0]);
                    float m1 = silu_mul(g[hf * 2 + 1], u[hf * 2 + 1]);
                    ushort2 h2v, l2v;
                    split2(m0, h2v.x, l2v.x);
                    split2(m1, h2v.y, l2v.y);
                    size_t off = (size_t)(row0 + wm + i * 16 + rin + hf * 8) * I_DIM + colb;
                    *(ushort2*)(d_midhi + off) = h2v;
                    *(ushort2*)(d_midlo + off) = l2v;
                }
            }
    } else {
#pragma unroll
        for (int i = 0; i < 4; i++)
#pragma unroll
            for (int j = 0; j < 4; j++) {
                float* p = d_eo + (size_t)(row0 + wm + i * 16 + rin) * H_DIM +
                           n0 + wn + j * 8 + cin;
                *(float2*)p = make_float2(acc[i][j][0], acc[i][j][1]);
                *(float2*)(p + 8 * (size_t)H_DIM) = make_float2(acc[i][j][2], acc[i][j][3]);
            }
    }
#undef LOAD_STAGE
}

// out[t] = w0*eo[row0] + w1*eo[row1]
__global__ void combine_kernel(float* __restrict__ out) {
    int t = blockIdx.x;
    int r0 = d_pairrow[t * 2 + 0], r1 = d_pairrow[t * 2 + 1];
    float w0 = d_topw[t * 2 + 0], w1 = d_topw[t * 2 + 1];
    int h4 = threadIdx.x;
    float4 a = ((const float4*)(d_eo + (size_t)r0 * H_DIM))[h4];
    float4 b = ((const float4*)(d_eo + (size_t)r1 * H_DIM))[h4];
    float4 o;
    o.x = w0 * a.x + w1 * b.x;
    o.y = w0 * a.y + w1 * b.y;
    o.z = w0 * a.z + w1 * b.z;
    o.w = w0 * a.w + w1 * b.w;
    ((float4*)(out + (size_t)t * H_DIM))[h4] = o;
}

// ---------------------------------------------------------------------------
extern "C" void kernel_launch(void* const* d_in, const int* in_sizes, int n_in,
                              void* d_out, int out_size) {
    const float* x  = (const float*)d_in[0];  // [4096, 1024]
    const float* gw = (const float*)d_in[1];  // [1024, 8]
    const float* Wg = (const float*)d_in[2];  // [8, 1024, 2048]
    const float* Wu = (const float*)d_in[3];  // [8, 1024, 2048]
    const float* Wd = (const float*)d_in[4];  // [8, 2048, 1024]
    float* out = (float*)d_out;               // final (4194304) then logits (32768)
    float* out_logits = out + (size_t)T_TOK * H_DIM;

    cudaFuncSetAttribute(mma_gemm_kernel<0>, cudaFuncAttributeMaxDynamicSharedMemorySize, SMEM_TOTAL);
    cudaFuncSetAttribute(mma_gemm_kernel<1>, cudaFuncAttributeMaxDynamicSharedMemorySize, SMEM_TOTAL);

    init_kernel<<<1, 256>>>();
    convx_kernel<<<(T_TOK * H_DIM / 4) / 256, 256>>>(x);
    wtrans_kernel<<<dim3(I_DIM / 32, H_DIM / 64, N_EXP), 256>>>(Wg, 0);
    wtrans_kernel<<<dim3(I_DIM / 32, H_DIM / 64, N_EXP), 256>>>(Wu, 1);
    wtrans_kernel<<<dim3(H_DIM / 32, I_DIM / 64, N_EXP), 256>>>(Wd, 2);

    router_kernel<<<T_TOK / 8, 256>>>(x, gw, out_logits);
    scan_kernel<<<1, 32>>>();
    scatter_kernel<<<T_TOK / 256, 256>>>();

    // GEMM1 (fused act): [rows,1024] x W1^T -> d_mid (bf16 hi/lo)
    mma_gemm_kernel<0><<<dim3(MAXROWS / BM, (2 * I_DIM) / BN), 256, SMEM_TOTAL>>>();
    // GEMM2: [rows,2048] x Wd^T -> d_eo
    mma_gemm_kernel<1><<<dim3(MAXROWS / BM, H_DIM / BN), 256, SMEM_TOTAL>>>();
    combine_kernel<<<T_TOK, 256>>>(out);
}

// round 6
// speedup vs baseline: 1.1535x; 1.1535x over previous
#include <cuda_runtime.h>
#include <cuda_bf16.h>
#include <cstdint>
#include <math.h>

// ---------------------------------------------------------------------------
// Problem constants
#define T_TOK 4096
#define H_DIM 1024
#define I_DIM 2048
#define N_EXP 8
#define K_TOP 2
#define MAXROWS 10240   // 8192 pairs + per-expert padding to 128 => 80 tiles

// GEMM tiling
#define BM 128
#define BN 128
#define BK 32
#define ROWB 80                      // padded smem row: 32 bf16 (64B) + 16B pad
#define TILE_BYTES (128 * ROWB)      // 10240
#define STAGE_BYTES (4 * TILE_BYTES) // Ahi, Alo, Bhi, Blo
#define SMEM_TOTAL (2 * STAGE_BYTES) // 81920 -> 2 CTAs/SM

// ---------------------------------------------------------------------------
// Scratch (device globals — allocation-free; referenced ONLY from device code)
__device__ int   d_count[N_EXP];
__device__ int   d_cursor[N_EXP];
__device__ int   d_seg[N_EXP + 1];
__device__ int   d_tok[MAXROWS];
__device__ int   d_pairrow[T_TOK * K_TOP];
__device__ float d_topw[T_TOK * K_TOP];
__device__ int   d_tope[T_TOK * K_TOP];

__device__ unsigned short d_xhi[(size_t)T_TOK * H_DIM];
__device__ unsigned short d_xlo[(size_t)T_TOK * H_DIM];
// W1 = gate/up interleaved at 8-col granularity: [E][4096][1024]
//   gate col j -> n' = (j>>3)*16 + (j&7);  up col j -> n' = (j>>3)*16 + 8 + (j&7)
__device__ unsigned short d_W1hi[(size_t)N_EXP * 2 * I_DIM * H_DIM];
__device__ unsigned short d_W1lo[(size_t)N_EXP * 2 * I_DIM * H_DIM];
// Wd transposed: [E][1024][2048]
__device__ unsigned short d_Wdhi[(size_t)N_EXP * H_DIM * I_DIM];
__device__ unsigned short d_Wdlo[(size_t)N_EXP * H_DIM * I_DIM];
__device__ unsigned short d_midhi[(size_t)MAXROWS * I_DIM];
__device__ unsigned short d_midlo[(size_t)MAXROWS * I_DIM];
__device__ float d_eo[(size_t)MAXROWS * H_DIM];

// ---------------------------------------------------------------------------
// PTX macros (baseline PTX only: compiles for compute_103 target)
#define CP16(dst, src, sz) \
    asm volatile("cp.async.cg.shared.global [%0], [%1], 16, %2;" \
                 :: "r"(dst), "l"(src), "r"(sz) : "memory")
#define CP_COMMIT() asm volatile("cp.async.commit_group;" ::: "memory")
#define CP_WAIT1()  asm volatile("cp.async.wait_group 1;" ::: "memory")
#define CP_WAIT0()  asm volatile("cp.async.wait_group 0;" ::: "memory")

#define LDSM_X4(r, addr) \
    asm volatile("ldmatrix.sync.aligned.m8n8.x4.shared.b16 {%0,%1,%2,%3}, [%4];" \
                 : "=r"((r)[0]), "=r"((r)[1]), "=r"((r)[2]), "=r"((r)[3]) : "r"(addr))

#define MMA_BF16(c, a, b) \
    asm volatile("mma.sync.aligned.m16n8k16.row.col.f32.bf16.bf16.f32 " \
                 "{%0,%1,%2,%3}, {%4,%5,%6,%7}, {%8,%9}, {%0,%1,%2,%3};" \
                 : "+f"((c)[0]), "+f"((c)[1]), "+f"((c)[2]), "+f"((c)[3]) \
                 : "r"((a)[0]), "r"((a)[1]), "r"((a)[2]), "r"((a)[3]), \
                   "r"((b)[0]), "r"((b)[1]))

// bf16 split helpers
__device__ __forceinline__ unsigned short bfbits(float v) {
    __nv_bfloat16 b = __float2bfloat16_rn(v);
    return *reinterpret_cast<unsigned short*>(&b);
}
__device__ __forceinline__ float bfval(unsigned short u) {
    __nv_bfloat16 b;
    *reinterpret_cast<unsigned short*>(&b) = u;
    return __bfloat162float(b);
}
__device__ __forceinline__ void split2(float v, unsigned short& h, unsigned short& l) {
    h = bfbits(v);
    l = bfbits(v - bfval(h));
}
__device__ __forceinline__ float silu_mul(float g, float u) {
    return g / (1.f + expf(-g)) * u;
}

// ---------------------------------------------------------------------------
__global__ void init_kernel() {
    int tid = threadIdx.x;
    if (tid < N_EXP) { d_count[tid] = 0; d_cursor[tid] = 0; }
    for (int i = tid; i < MAXROWS; i += blockDim.x) d_tok[i] = -1;
}

// fp32 x -> bf16 hi/lo
__global__ void convx_kernel(const float* __restrict__ x) {
    size_t i = (size_t)blockIdx.x * 256 + threadIdx.x;  // float4 index
    float4 v = ((const float4*)x)[i];
    ushort4 h, l;
    split2(v.x, h.x, l.x); split2(v.y, h.y, l.y);
    split2(v.z, h.z, l.z); split2(v.w, h.w, l.w);
    ((ushort4*)d_xhi)[i] = h;
    ((ushort4*)d_xlo)[i] = l;
}

// transpose + hi/lo split with vectorized writes.
// mode 0: Wg -> W1 (interleaved even groups); 1: Wu -> W1 (odd); 2: Wd.
__global__ void wtrans_kernel(const float* __restrict__ W, int mode) {
    __shared__ float tile[64][33];
    const int Kd = (mode == 2) ? I_DIM : H_DIM;
    const int Nd = (mode == 2) ? H_DIM : I_DIM;
    const int Nb = (mode == 2) ? H_DIM : 2 * I_DIM;
    unsigned short* Thi = (mode == 2) ? d_Wdhi : d_W1hi;
    unsigned short* Tlo = (mode == 2) ? d_Wdlo : d_W1lo;

    int e = blockIdx.z;
    const float* We = W + (size_t)e * Kd * Nd;
    int nbase = blockIdx.x * 32, kbase = blockIdx.y * 64;
    int tid = threadIdx.x, tx = tid & 31, ty = tid >> 5;
#pragma unroll
    for (int r = 0; r < 64; r += 8)
        tile[r + ty][tx] = We[(size_t)(kbase + r + ty) * Nd + nbase + tx];
    __syncthreads();

    size_t ebase = (size_t)e * Nb * Kd;
#pragma unroll
    for (int task = tid; task < 512; task += 256) {
        int n = task >> 4, q = task & 15;
        int j = nbase + n;
        int np = (mode == 2) ? j
                 : (((j >> 3) << 4) | (mode == 1 ? 8 : 0) | (j & 7));
        ushort4 h, l;
        split2(tile[q * 4 + 0][n], h.x, l.x);
        split2(tile[q * 4 + 1][n], h.y, l.y);
        split2(tile[q * 4 + 2][n], h.z, l.z);
        split2(tile[q * 4 + 3][n], h.w, l.w);
        size_t o = ebase + (size_t)np * Kd + kbase + q * 4;
        *(ushort4*)(Thi + o) = h;
        *(ushort4*)(Tlo + o) = l;
    }
}

// One warp per token: logits, softmax, top-2, expert counting.
__global__ void router_kernel(const float* __restrict__ x,
                              const float* __restrict__ gw,
                              float* __restrict__ out_logits) {
    int warp = threadIdx.x >> 5, lane = threadIdx.x & 31;
    int t = blockIdx.x * 8 + warp;
    if (t >= T_TOK) return;
    const float* xr = x + (size_t)t * H_DIM;
    float acc[N_EXP];
#pragma unroll
    for (int e = 0; e < N_EXP; e++) acc[e] = 0.f;
    for (int i = lane; i < H_DIM; i += 32) {
        float xv = xr[i];
        float4 a = __ldg((const float4*)(gw + (size_t)i * N_EXP));
        float4 b = __ldg((const float4*)(gw + (size_t)i * N_EXP) + 1);
        acc[0] += xv * a.x; acc[1] += xv * a.y; acc[2] += xv * a.z; acc[3] += xv * a.w;
        acc[4] += xv * b.x; acc[5] += xv * b.y; acc[6] += xv * b.z; acc[7] += xv * b.w;
    }
#pragma unroll
    for (int off = 16; off > 0; off >>= 1)
#pragma unroll
        for (int e = 0; e < N_EXP; e++)
            acc[e] += __shfl_xor_sync(0xffffffffu, acc[e], off);
    if (lane == 0) {
#pragma unroll
        for (int e = 0; e < N_EXP; e++) out_logits[(size_t)t * N_EXP + e] = acc[e];
        float m = acc[0];
#pragma unroll
        for (int e = 1; e < N_EXP; e++) m = fmaxf(m, acc[e]);
        float p[N_EXP], s = 0.f;
#pragma unroll
        for (int e = 0; e < N_EXP; e++) { p[e] = expf(acc[e] - m); s += p[e]; }
        float inv = 1.f / s;
        int i0 = 0; float b0 = p[0];
#pragma unroll
        for (int e = 1; e < N_EXP; e++) if (p[e] > b0) { b0 = p[e]; i0 = e; }
        int i1 = -1; float b1 = -1.f;
#pragma unroll
        for (int e = 0; e < N_EXP; e++) if (e != i0 && p[e] > b1) { b1 = p[e]; i1 = e; }
        d_tope[t * 2 + 0] = i0; d_topw[t * 2 + 0] = b0 * inv;
        d_tope[t * 2 + 1] = i1; d_topw[t * 2 + 1] = b1 * inv;
        atomicAdd(&d_count[i0], 1);
        atomicAdd(&d_count[i1], 1);
    }
}

__global__ void scan_kernel() {
    if (threadIdx.x == 0) {
        int off = 0;
#pragma unroll
        for (int e = 0; e < N_EXP; e++) { d_seg[e] = off; off += (d_count[e] + 127) & ~127; }
        d_seg[N_EXP] = off;
    }
}

__global__ void scatter_kernel() {
    int t = blockIdx.x * blockDim.x + threadIdx.x;
    if (t >= T_TOK) return;
#pragma unroll
    for (int k = 0; k < K_TOP; k++) {
        int e = d_tope[t * 2 + k];
        int pos = atomicAdd(&d_cursor[e], 1);
        int row = d_seg[e] + pos;
        d_tok[row] = t;
        d_pairrow[t * 2 + k] = row;
    }
}

// ---------------------------------------------------------------------------
// Grouped GEMM on mma.sync.m16n8k16 bf16, hi/lo split (3 passes), fp32 acc.
// MODE 0: A = gather(x) [K=1024], B = W1 (g/u interleaved), epilogue fuses
//         silu(g)*u -> bf16 hi/lo -> d_mid  (acc j even = gate, odd = up)
// MODE 1: A = mid [K=2048], B = Wd, C -> d_eo (fp32)
// 128x128x32 CTA tile, 8 warps of 64x32, 2-stage cp.async, 2 CTAs/SM.
template <int MODE>
__global__ __launch_bounds__(256, 2)
void mma_gemm_kernel()
{
    constexpr int Kdim = (MODE == 0) ? H_DIM : I_DIM;
    constexpr int Nb   = (MODE == 0) ? 2 * I_DIM : H_DIM;

    extern __shared__ char sm[];
    int row0 = blockIdx.x * BM;
    if (row0 >= d_seg[N_EXP]) return;

    const unsigned short* __restrict__ Ahi_g = (MODE == 0) ? d_xhi : d_midhi;
    const unsigned short* __restrict__ Alo_g = (MODE == 0) ? d_xlo : d_midlo;
    const unsigned short* __restrict__ Bhi_g = (MODE == 0) ? d_W1hi : d_Wdhi;
    const unsigned short* __restrict__ Blo_g = (MODE == 0) ? d_W1lo : d_Wdlo;

    uint32_t sbase = (uint32_t)__cvta_generic_to_shared(sm);
    int tid = threadIdx.x, lane = tid & 31, wid = tid >> 5;
    int n0 = blockIdx.y * BN;

    int e = 0;
#pragma unroll
    for (int i = 0; i < N_EXP - 1; i++) if (row0 >= d_seg[i + 1]) e = i + 1;

    // ---- per-thread load setup: 2 rows per tile (r and r+64), 16B chunk kc
    int r1 = tid >> 2, kc = tid & 3;
    const unsigned short *pAh[2], *pAl[2], *pBh[2], *pBl[2];
    uint32_t szA[2], dstoff[2];
#pragma unroll
    for (int h2 = 0; h2 < 2; h2++) {
        int r = r1 + h2 * 64;
        dstoff[h2] = (uint32_t)(r * ROWB + kc * 16);
        if (MODE == 0) {
            int tok = d_tok[row0 + r];
            if (tok >= 0) {
                pAh[h2] = Ahi_g + (size_t)tok * Kdim + kc * 8;
                pAl[h2] = Alo_g + (size_t)tok * Kdim + kc * 8;
                szA[h2] = 16;
            } else {
                pAh[h2] = Ahi_g; pAl[h2] = Alo_g; szA[h2] = 0;  // zero-fill
            }
        } else {
            pAh[h2] = Ahi_g + (size_t)(row0 + r) * Kdim + kc * 8;
            pAl[h2] = Alo_g + (size_t)(row0 + r) * Kdim + kc * 8;
            szA[h2] = 16;
        }
        size_t bo = ((size_t)e * Nb + n0 + r) * Kdim + kc * 8;
        pBh[h2] = Bhi_g + bo;
        pBl[h2] = Blo_g + bo;
    }

#define LOAD_STAGE(s, kof) do { \
    uint32_t sb_ = sbase + (s) * STAGE_BYTES; \
    _Pragma("unroll") \
    for (int h2 = 0; h2 < 2; h2++) { \
        CP16(sb_ + 0 * TILE_BYTES + dstoff[h2], pAh[h2] + (kof), szA[h2]); \
        CP16(sb_ + 1 * TILE_BYTES + dstoff[h2], pAl[h2] + (kof), szA[h2]); \
        CP16(sb_ + 2 * TILE_BYTES + dstoff[h2], pBh[h2] + (kof), 16u); \
        CP16(sb_ + 3 * TILE_BYTES + dstoff[h2], pBl[h2] + (kof), 16u); \
    } \
} while (0)

    // ---- compute setup
    int wm = (wid & 1) * 64, wn = (wid >> 1) * 32;
    uint32_t a_off = (uint32_t)((wm + (lane & 15)) * ROWB + (lane >> 4) * 16);
    uint32_t b_off = (uint32_t)((wn + (lane & 7) + ((lane >> 4) << 3)) * ROWB +
                                ((lane >> 3) & 1) * 16);

    float acc[4][4][4];
#pragma unroll
    for (int i = 0; i < 4; i++)
#pragma unroll
        for (int j = 0; j < 4; j++)
#pragma unroll
            for (int q = 0; q < 4; q++) acc[i][j][q] = 0.f;

    const int nk = Kdim / BK;
    LOAD_STAGE(0, 0);
    CP_COMMIT();

    for (int ks = 0; ks < nk; ks++) {
        int s = ks & 1;
        if (ks + 1 < nk) {
            LOAD_STAGE(s ^ 1, (ks + 1) * BK);
            CP_COMMIT();
            CP_WAIT1();
        } else {
            CP_WAIT0();
        }
        __syncthreads();

        uint32_t sb = sbase + s * STAGE_BYTES;
#pragma unroll
        for (int h = 0; h < 2; h++) {  // two k16 steps per BK=32
            // B fragments first (16 regs live), then A per-i (8 regs transient)
            uint32_t bh[4][2], bl[4][2];
#pragma unroll
            for (int jp = 0; jp < 2; jp++) {
                uint32_t tmp[4];
                uint32_t bd = sb + 2 * TILE_BYTES + b_off + jp * (16 * ROWB) + h * 32;
                LDSM_X4(tmp, bd);
                bh[jp * 2][0] = tmp[0]; bh[jp * 2][1] = tmp[1];
                bh[jp * 2 + 1][0] = tmp[2]; bh[jp * 2 + 1][1] = tmp[3];
                LDSM_X4(tmp, bd + TILE_BYTES);
                bl[jp * 2][0] = tmp[0]; bl[jp * 2][1] = tmp[1];
                bl[jp * 2 + 1][0] = tmp[2]; bl[jp * 2 + 1][1] = tmp[3];
            }
#pragma unroll
            for (int i = 0; i < 4; i++) {
                uint32_t ah[4], al[4];
                uint32_t ad = sb + a_off + i * (16 * ROWB) + h * 32;
                LDSM_X4(ah, ad);
                LDSM_X4(al, ad + TILE_BYTES);
#pragma unroll
                for (int j = 0; j < 4; j++) {
                    MMA_BF16(acc[i][j], ah, bh[j]);
                    MMA_BF16(acc[i][j], ah, bl[j]);
                    MMA_BF16(acc[i][j], al, bh[j]);
                }
            }
        }
        __syncthreads();
    }

    // ---- epilogue
    int rin = lane >> 2, cin = (lane & 3) * 2;
    if (MODE == 0) {
        // acc[i][jp*2] = gate, acc[i][jp*2+1] = up for the SAME logical cols
        int midcol0 = (n0 + wn) >> 1;  // logical mid col base for this warp
#pragma unroll
        for (int i = 0; i < 4; i++)
#pragma unroll
            for (int jp = 0; jp < 2; jp++) {
                const float* g = acc[i][jp * 2];
                const float* u = acc[i][jp * 2 + 1];
                int colb = midcol0 + jp * 8 + cin;
#pragma unroll
                for (int hf = 0; hf < 2; hf++) {
                    float m0 = silu_mul(g[hf * 2 + 0], u[hf * 2 + 0]);
                    float m1 = silu_mul(g[hf * 2 + 1], u[hf * 2 + 1]);
                    ushort2 h2v, l2v;
                    split2(m0, h2v.x, l2v.x);
                    split2(m1, h2v.y, l2v.y);
                    size_t off = (size_t)(row0 + wm + i * 16 + rin + hf * 8) * I_DIM + colb;
                    *(ushort2*)(d_midhi + off) = h2v;
                    *(ushort2*)(d_midlo + off) = l2v;
                }
            }
    } else {
#pragma unroll
        for (int i = 0; i < 4; i++)
#pragma unroll
            for (int j = 0; j < 4; j++) {
                float* p = d_eo + (size_t)(row0 + wm + i * 16 + rin) * H_DIM +
                           n0 + wn + j * 8 + cin;
                *(float2*)p = make_float2(acc[i][j][0], acc[i][j][1]);
                *(float2*)(p + 8 * (size_t)H_DIM) = make_float2(acc[i][j][2], acc[i][j][3]);
            }
    }
#undef LOAD_STAGE
}

// out[t] = w0*eo[row0] + w1*eo[row1]
__global__ void combine_kernel(float* __restrict__ out) {
    int t = blockIdx.x;
    int r0 = d_pairrow[t * 2 + 0], r1 = d_pairrow[t * 2 + 1];
    float w0 = d_topw[t * 2 + 0], w1 = d_topw[t * 2 + 1];
    int h4 = threadIdx.x;
    float4 a = ((const float4*)(d_eo + (size_t)r0 * H_DIM))[h4];
    float4 b = ((const float4*)(d_eo + (size_t)r1 * H_DIM))[h4];
    float4 o;
    o.x = w0 * a.x + w1 * b.x;
    o.y = w0 * a.y + w1 * b.y;
    o.z = w0 * a.z + w1 * b.z;
    o.w = w0 * a.w + w1 * b.w;
    ((float4*)(out + (size_t)t * H_DIM))[h4] = o;
}

// ---------------------------------------------------------------------------
extern "C" void kernel_launch(void* const* d_in, const int* in_sizes, int n_in,
                              void* d_out, int out_size) {
    const float* x  = (const float*)d_in[0];  // [4096, 1024]
    const float* gw = (const float*)d_in[1];  // [1024, 8]
    const float* Wg = (const float*)d_in[2];  // [8, 1024, 2048]
    const float* Wu = (const float*)d_in[3];  // [8, 1024, 2048]
    const float* Wd = (const float*)d_in[4];  // [8, 2048, 1024]
    float* out = (float*)d_out;               // final (4194304) then logits (32768)
    float* out_logits = out + (size_t)T_TOK * H_DIM;

    cudaFuncSetAttribute(mma_gemm_kernel<0>, cudaFuncAttributeMaxDynamicSharedMemorySize, SMEM_TOTAL);
    cudaFuncSetAttribute(mma_gemm_kernel<1>, cudaFuncAttributeMaxDynamicSharedMemorySize, SMEM_TOTAL);

    init_kernel<<<1, 256>>>();
    convx_kernel<<<(T_TOK * H_DIM / 4) / 256, 256>>>(x);
    wtrans_kernel<<<dim3(I_DIM / 32, H_DIM / 64, N_EXP), 256>>>(Wg, 0);
    wtrans_kernel<<<dim3(I_DIM / 32, H_DIM / 64, N_EXP), 256>>>(Wu, 1);
    wtrans_kernel<<<dim3(H_DIM / 32, I_DIM / 64, N_EXP), 256>>>(Wd, 2);

    router_kernel<<<T_TOK / 8, 256>>>(x, gw, out_logits);
    scan_kernel<<<1, 32>>>();
    scatter_kernel<<<T_TOK / 256, 256>>>();

    // GEMM1 (fused act): [rows,1024] x W1^T -> d_mid (bf16 hi/lo)
    mma_gemm_kernel<0><<<dim3(MAXROWS / BM, (2 * I_DIM) / BN), 256, SMEM_TOTAL>>>();
    // GEMM2: [rows,2048] x Wd^T -> d_eo
    mma_gemm_kernel<1><<<dim3(MAXROWS / BM, H_DIM / BN), 256, SMEM_TOTAL>>>();
    combine_kernel<<<T_TOK, 256>>>(out);
}

// round 7
// speedup vs baseline: 1.1636x; 1.0088x over previous
#include <cuda_runtime.h>
#include <cuda_bf16.h>
#include <cstdint>
#include <math.h>

// ---------------------------------------------------------------------------
// Problem constants
#define T_TOK 4096
#define H_DIM 1024
#define I_DIM 2048
#define N_EXP 8
#define K_TOP 2
#define MAXROWS 10240   // 8192 pairs + per-expert padding to 128 => 80 tiles

// GEMM tiling
#define BM 128
#define BN 128
#define BK 32
#define ROWB 80                      // padded smem row: 32 bf16 (64B) + 16B pad
#define TILE_BYTES (128 * ROWB)      // 10240
#define STAGE_BYTES (4 * TILE_BYTES) // Ahi, Alo, Bhi, Blo
#define SMEM_TOTAL (2 * STAGE_BYTES) // 81920 -> 2 CTAs/SM

// ---------------------------------------------------------------------------
// Scratch (device globals — allocation-free; referenced ONLY from device code)
__device__ int   d_count[N_EXP];
__device__ int   d_cursor[N_EXP];
__device__ int   d_seg[N_EXP + 1];
__device__ int   d_tok[MAXROWS];
__device__ float d_roww[MAXROWS];            // combine weight per expert-row
__device__ float d_topw[T_TOK * K_TOP];
__device__ int   d_tope[T_TOK * K_TOP];

__device__ unsigned short d_xhi[(size_t)T_TOK * H_DIM];
__device__ unsigned short d_xlo[(size_t)T_TOK * H_DIM];
// W1 = gate/up interleaved at 8-col granularity: [E][4096][1024]
//   gate col j -> n' = (j>>3)*16 + (j&7);  up col j -> n' = (j>>3)*16 + 8 + (j&7)
__device__ unsigned short d_W1hi[(size_t)N_EXP * 2 * I_DIM * H_DIM];
__device__ unsigned short d_W1lo[(size_t)N_EXP * 2 * I_DIM * H_DIM];
// Wd transposed: [E][1024][2048]
__device__ unsigned short d_Wdhi[(size_t)N_EXP * H_DIM * I_DIM];
__device__ unsigned short d_Wdlo[(size_t)N_EXP * H_DIM * I_DIM];
__device__ unsigned short d_midhi[(size_t)MAXROWS * I_DIM];
__device__ unsigned short d_midlo[(size_t)MAXROWS * I_DIM];

// ---------------------------------------------------------------------------
// PTX macros (baseline PTX only: compiles for compute_103 target)
#define CP16(dst, src, sz) \
    asm volatile("cp.async.cg.shared.global [%0], [%1], 16, %2;" \
                 :: "r"(dst), "l"(src), "r"(sz) : "memory")
#define CP_COMMIT() asm volatile("cp.async.commit_group;" ::: "memory")
#define CP_WAIT1()  asm volatile("cp.async.wait_group 1;" ::: "memory")
#define CP_WAIT0()  asm volatile("cp.async.wait_group 0;" ::: "memory")

#define LDSM_X4(r, addr) \
    asm volatile("ldmatrix.sync.aligned.m8n8.x4.shared.b16 {%0,%1,%2,%3}, [%4];" \
                 : "=r"((r)[0]), "=r"((r)[1]), "=r"((r)[2]), "=r"((r)[3]) : "r"(addr))

#define MMA_BF16(c, a, b) \
    asm volatile("mma.sync.aligned.m16n8k16.row.col.f32.bf16.bf16.f32 " \
                 "{%0,%1,%2,%3}, {%4,%5,%6,%7}, {%8,%9}, {%0,%1,%2,%3};" \
                 : "+f"((c)[0]), "+f"((c)[1]), "+f"((c)[2]), "+f"((c)[3]) \
                 : "r"((a)[0]), "r"((a)[1]), "r"((a)[2]), "r"((a)[3]), \
                   "r"((b)[0]), "r"((b)[1]))

// bf16 split helpers
__device__ __forceinline__ unsigned short bfbits(float v) {
    __nv_bfloat16 b = __float2bfloat16_rn(v);
    return *reinterpret_cast<unsigned short*>(&b);
}
__device__ __forceinline__ float bfval(unsigned short u) {
    __nv_bfloat16 b;
    *reinterpret_cast<unsigned short*>(&b) = u;
    return __bfloat162float(b);
}
__device__ __forceinline__ void split2(float v, unsigned short& h, unsigned short& l) {
    h = bfbits(v);
    l = bfbits(v - bfval(h));
}
__device__ __forceinline__ float silu_mul(float g, float u) {
    return g / (1.f + expf(-g)) * u;
}

// ---------------------------------------------------------------------------
__global__ void init_kernel() {
    int tid = threadIdx.x;
    if (tid < N_EXP) { d_count[tid] = 0; d_cursor[tid] = 0; }
    for (int i = tid; i < MAXROWS; i += blockDim.x) d_tok[i] = -1;
}

// zero the final-output region (harness poisons d_out with 0xAA)
__global__ void zero_out_kernel(float* __restrict__ out) {
    size_t i = (size_t)blockIdx.x * 256 + threadIdx.x;
    ((float4*)out)[i] = make_float4(0.f, 0.f, 0.f, 0.f);
}

// fp32 x -> bf16 hi/lo
__global__ void convx_kernel(const float* __restrict__ x) {
    size_t i = (size_t)blockIdx.x * 256 + threadIdx.x;  // float4 index
    float4 v = ((const float4*)x)[i];
    ushort4 h, l;
    split2(v.x, h.x, l.x); split2(v.y, h.y, l.y);
    split2(v.z, h.z, l.z); split2(v.w, h.w, l.w);
    ((ushort4*)d_xhi)[i] = h;
    ((ushort4*)d_xlo)[i] = l;
}

// transpose + hi/lo split with vectorized writes.
// mode 0: Wg -> W1 (interleaved even groups); 1: Wu -> W1 (odd); 2: Wd.
__global__ void wtrans_kernel(const float* __restrict__ W, int mode) {
    __shared__ float tile[64][33];
    const int Kd = (mode == 2) ? I_DIM : H_DIM;
    const int Nd = (mode == 2) ? H_DIM : I_DIM;
    const int Nb = (mode == 2) ? H_DIM : 2 * I_DIM;
    unsigned short* Thi = (mode == 2) ? d_Wdhi : d_W1hi;
    unsigned short* Tlo = (mode == 2) ? d_Wdlo : d_W1lo;

    int e = blockIdx.z;
    const float* We = W + (size_t)e * Kd * Nd;
    int nbase = blockIdx.x * 32, kbase = blockIdx.y * 64;
    int tid = threadIdx.x, tx = tid & 31, ty = tid >> 5;
#pragma unroll
    for (int r = 0; r < 64; r += 8)
        tile[r + ty][tx] = We[(size_t)(kbase + r + ty) * Nd + nbase + tx];
    __syncthreads();

    size_t ebase = (size_t)e * Nb * Kd;
#pragma unroll
    for (int task = tid; task < 512; task += 256) {
        int n = task >> 4, q = task & 15;
        int j = nbase + n;
        int np = (mode == 2) ? j
                 : (((j >> 3) << 4) | (mode == 1 ? 8 : 0) | (j & 7));
        ushort4 h, l;
        split2(tile[q * 4 + 0][n], h.x, l.x);
        split2(tile[q * 4 + 1][n], h.y, l.y);
        split2(tile[q * 4 + 2][n], h.z, l.z);
        split2(tile[q * 4 + 3][n], h.w, l.w);
        size_t o = ebase + (size_t)np * Kd + kbase + q * 4;
        *(ushort4*)(Thi + o) = h;
        *(ushort4*)(Tlo + o) = l;
    }
}

// One warp per token: logits, softmax, top-2, expert counting.
__global__ void router_kernel(const float* __restrict__ x,
                              const float* __restrict__ gw,
                              float* __restrict__ out_logits) {
    int warp = threadIdx.x >> 5, lane = threadIdx.x & 31;
    int t = blockIdx.x * 8 + warp;
    if (t >= T_TOK) return;
    const float* xr = x + (size_t)t * H_DIM;
    float acc[N_EXP];
#pragma unroll
    for (int e = 0; e < N_EXP; e++) acc[e] = 0.f;
    for (int i = lane; i < H_DIM; i += 32) {
        float xv = xr[i];
        float4 a = __ldg((const float4*)(gw + (size_t)i * N_EXP));
        float4 b = __ldg((const float4*)(gw + (size_t)i * N_EXP) + 1);
        acc[0] += xv * a.x; acc[1] += xv * a.y; acc[2] += xv * a.z; acc[3] += xv * a.w;
        acc[4] += xv * b.x; acc[5] += xv * b.y; acc[6] += xv * b.z; acc[7] += xv * b.w;
    }
#pragma unroll
    for (int off = 16; off > 0; off >>= 1)
#pragma unroll
        for (int e = 0; e < N_EXP; e++)
            acc[e] += __shfl_xor_sync(0xffffffffu, acc[e], off);
    if (lane == 0) {
#pragma unroll
        for (int e = 0; e < N_EXP; e++) out_logits[(size_t)t * N_EXP + e] = acc[e];
        float m = acc[0];
#pragma unroll
        for (int e = 1; e < N_EXP; e++) m = fmaxf(m, acc[e]);
        float p[N_EXP], s = 0.f;
#pragma unroll
        for (int e = 0; e < N_EXP; e++) { p[e] = expf(acc[e] - m); s += p[e]; }
        float inv = 1.f / s;
        int i0 = 0; float b0 = p[0];
#pragma unroll
        for (int e = 1; e < N_EXP; e++) if (p[e] > b0) { b0 = p[e]; i0 = e; }
        int i1 = -1; float b1 = -1.f;
#pragma unroll
        for (int e = 0; e < N_EXP; e++) if (e != i0 && p[e] > b1) { b1 = p[e]; i1 = e; }
        d_tope[t * 2 + 0] = i0; d_topw[t * 2 + 0] = b0 * inv;
        d_tope[t * 2 + 1] = i1; d_topw[t * 2 + 1] = b1 * inv;
        atomicAdd(&d_count[i0], 1);
        atomicAdd(&d_count[i1], 1);
    }
}

__global__ void scan_kernel() {
    if (threadIdx.x == 0) {
        int off = 0;
#pragma unroll
        for (int e = 0; e < N_EXP; e++) { d_seg[e] = off; off += (d_count[e] + 127) & ~127; }
        d_seg[N_EXP] = off;
    }
}

__global__ void scatter_kernel() {
    int t = blockIdx.x * blockDim.x + threadIdx.x;
    if (t >= T_TOK) return;
#pragma unroll
    for (int k = 0; k < K_TOP; k++) {
        int e = d_tope[t * 2 + k];
        int pos = atomicAdd(&d_cursor[e], 1);
        int row = d_seg[e] + pos;
        d_tok[row] = t;
        d_roww[row] = d_topw[t * 2 + k];
    }
}

// ---------------------------------------------------------------------------
// Grouped GEMM on mma.sync.m16n8k16 bf16, hi/lo split (3 passes), fp32 acc.
// MODE 0: A = gather(x) [K=1024], B = W1 (g/u interleaved), epilogue fuses
//         silu(g)*u -> bf16 hi/lo -> d_mid  (acc j even = gate, odd = up)
// MODE 1: A = mid [K=2048], B = Wd, epilogue fuses weighted combine:
//         out[token] += w_row * acc  (atomicAdd; exactly 2 adds/element ->
//         commutative -> deterministic)
// 128x128x32 CTA tile, 8 warps of 64x32, 2-stage cp.async, 2 CTAs/SM.
template <int MODE>
__global__ __launch_bounds__(256, 2)
void mma_gemm_kernel(float* __restrict__ out)
{
    constexpr int Kdim = (MODE == 0) ? H_DIM : I_DIM;
    constexpr int Nb   = (MODE == 0) ? 2 * I_DIM : H_DIM;

    extern __shared__ char sm[];
    int row0 = blockIdx.x * BM;
    if (row0 >= d_seg[N_EXP]) return;

    const unsigned short* __restrict__ Ahi_g = (MODE == 0) ? d_xhi : d_midhi;
    const unsigned short* __restrict__ Alo_g = (MODE == 0) ? d_xlo : d_midlo;
    const unsigned short* __restrict__ Bhi_g = (MODE == 0) ? d_W1hi : d_Wdhi;
    const unsigned short* __restrict__ Blo_g = (MODE == 0) ? d_W1lo : d_Wdlo;

    uint32_t sbase = (uint32_t)__cvta_generic_to_shared(sm);
    int tid = threadIdx.x, lane = tid & 31, wid = tid >> 5;
    int n0 = blockIdx.y * BN;

    int e = 0;
#pragma unroll
    for (int i = 0; i < N_EXP - 1; i++) if (row0 >= d_seg[i + 1]) e = i + 1;

    // ---- per-thread load setup: 2 rows per tile (r and r+64), 16B chunk kc
    int r1 = tid >> 2, kc = tid & 3;
    const unsigned short *pAh[2], *pAl[2], *pBh[2], *pBl[2];
    uint32_t szA[2], dstoff[2];
#pragma unroll
    for (int h2 = 0; h2 < 2; h2++) {
        int r = r1 + h2 * 64;
        dstoff[h2] = (uint32_t)(r * ROWB + kc * 16);
        if (MODE == 0) {
            int tok = d_tok[row0 + r];
            if (tok >= 0) {
                pAh[h2] = Ahi_g + (size_t)tok * Kdim + kc * 8;
                pAl[h2] = Alo_g + (size_t)tok * Kdim + kc * 8;
                szA[h2] = 16;
            } else {
                pAh[h2] = Ahi_g; pAl[h2] = Alo_g; szA[h2] = 0;  // zero-fill
            }
        } else {
            pAh[h2] = Ahi_g + (size_t)(row0 + r) * Kdim + kc * 8;
            pAl[h2] = Alo_g + (size_t)(row0 + r) * Kdim + kc * 8;
            szA[h2] = 16;
        }
        size_t bo = ((size_t)e * Nb + n0 + r) * Kdim + kc * 8;
        pBh[h2] = Bhi_g + bo;
        pBl[h2] = Blo_g + bo;
    }

#define LOAD_STAGE(s, kof) do { \
    uint32_t sb_ = sbase + (s) * STAGE_BYTES; \
    _Pragma("unroll") \
    for (int h2 = 0; h2 < 2; h2++) { \
        CP16(sb_ + 0 * TILE_BYTES + dstoff[h2], pAh[h2] + (kof), szA[h2]); \
        CP16(sb_ + 1 * TILE_BYTES + dstoff[h2], pAl[h2] + (kof), szA[h2]); \
        CP16(sb_ + 2 * TILE_BYTES + dstoff[h2], pBh[h2] + (kof), 16u); \
        CP16(sb_ + 3 * TILE_BYTES + dstoff[h2], pBl[h2] + (kof), 16u); \
    } \
} while (0)

    // ---- compute setup
    int wm = (wid & 1) * 64, wn = (wid >> 1) * 32;
    uint32_t a_off = (uint32_t)((wm + (lane & 15)) * ROWB + (lane >> 4) * 16);
    uint32_t b_off = (uint32_t)((wn + (lane & 7) + ((lane >> 4) << 3)) * ROWB +
                                ((lane >> 3) & 1) * 16);

    float acc[4][4][4];
#pragma unroll
    for (int i = 0; i < 4; i++)
#pragma unroll
        for (int j = 0; j < 4; j++)
#pragma unroll
            for (int q = 0; q < 4; q++) acc[i][j][q] = 0.f;

    const int nk = Kdim / BK;
    LOAD_STAGE(0, 0);
    CP_COMMIT();

    for (int ks = 0; ks < nk; ks++) {
        int s = ks & 1;
        if (ks + 1 < nk) {
            LOAD_STAGE(s ^ 1, (ks + 1) * BK);
            CP_COMMIT();
            CP_WAIT1();
        } else {
            CP_WAIT0();
        }
        __syncthreads();

        uint32_t sb = sbase + s * STAGE_BYTES;
#pragma unroll
        for (int h = 0; h < 2; h++) {  // two k16 steps per BK=32
            // B fragments first (16 regs live), then A per-i (8 regs transient)
            uint32_t bh[4][2], bl[4][2];
#pragma unroll
            for (int jp = 0; jp < 2; jp++) {
                uint32_t tmp[4];
                uint32_t bd = sb + 2 * TILE_BYTES + b_off + jp * (16 * ROWB) + h * 32;
                LDSM_X4(tmp, bd);
                bh[jp * 2][0] = tmp[0]; bh[jp * 2][1] = tmp[1];
                bh[jp * 2 + 1][0] = tmp[2]; bh[jp * 2 + 1][1] = tmp[3];
                LDSM_X4(tmp, bd + TILE_BYTES);
                bl[jp * 2][0] = tmp[0]; bl[jp * 2][1] = tmp[1];
                bl[jp * 2 + 1][0] = tmp[2]; bl[jp * 2 + 1][1] = tmp[3];
            }
#pragma unroll
            for (int i = 0; i < 4; i++) {
                uint32_t ah[4], al[4];
                uint32_t ad = sb + a_off + i * (16 * ROWB) + h * 32;
                LDSM_X4(ah, ad);
                LDSM_X4(al, ad + TILE_BYTES);
#pragma unroll
                for (int j = 0; j < 4; j++) {
                    MMA_BF16(acc[i][j], ah, bh[j]);
                    MMA_BF16(acc[i][j], ah, bl[j]);
                    MMA_BF16(acc[i][j], al, bh[j]);
                }
            }
        }
        __syncthreads();
    }

    // ---- epilogue
    int rin = lane >> 2, cin = (lane & 3) * 2;
    if (MODE == 0) {
        // acc[i][jp*2] = gate, acc[i][jp*2+1] = up for the SAME logical cols
        int midcol0 = (n0 + wn) >> 1;  // logical mid col base for this warp
#pragma unroll
        for (int i = 0; i < 4; i++)
#pragma unroll
            for (int jp = 0; jp < 2; jp++) {
                const float* g = acc[i][jp * 2];
                const float* u = acc[i][jp * 2 + 1];
                int colb = midcol0 + jp * 8 + cin;
#pragma unroll
                for (int hf = 0; hf < 2; hf++) {
                    float m0 = silu_mul(g[hf * 2 + 0], u[hf * 2 + 0]);
                    float m1 = silu_mul(g[hf * 2 + 1], u[hf * 2 + 1]);
                    ushort2 h2v, l2v;
                    split2(m0, h2v.x, l2v.x);
                    split2(m1, h2v.y, l2v.y);
                    size_t off = (size_t)(row0 + wm + i * 16 + rin + hf * 8) * I_DIM + colb;
                    *(ushort2*)(d_midhi + off) = h2v;
                    *(ushort2*)(d_midlo + off) = l2v;
                }
            }
    } else {
        // fused combine: out[token] += w_row * acc  (2 adds/element total)
        int   tokA[4], tokB[4];
        float wA[4], wB[4];
#pragma unroll
        for (int i = 0; i < 4; i++) {
            int ra = row0 + wm + i * 16 + rin;
            tokA[i] = d_tok[ra];     wA[i] = d_roww[ra];
            tokB[i] = d_tok[ra + 8]; wB[i] = d_roww[ra + 8];
        }
#pragma unroll
        for (int i = 0; i < 4; i++)
#pragma unroll
            for (int j = 0; j < 4; j++) {
                int col = n0 + wn + j * 8 + cin;
                if (tokA[i] >= 0) {
                    float* p = out + (size_t)tokA[i] * H_DIM + col;
                    atomicAdd(p,     wA[i] * acc[i][j][0]);
                    atomicAdd(p + 1, wA[i] * acc[i][j][1]);
                }
                if (tokB[i] >= 0) {
                    float* p = out + (size_t)tokB[i] * H_DIM + col;
                    atomicAdd(p,     wB[i] * acc[i][j][2]);
                    atomicAdd(p + 1, wB[i] * acc[i][j][3]);
                }
            }
    }
#undef LOAD_STAGE
}

// ---------------------------------------------------------------------------
extern "C" void kernel_launch(void* const* d_in, const int* in_sizes, int n_in,
                              void* d_out, int out_size) {
    const float* x  = (const float*)d_in[0];  // [4096, 1024]
    const float* gw = (const float*)d_in[1];  // [1024, 8]
    const float* Wg = (const float*)d_in[2];  // [8, 1024, 2048]
    const float* Wu = (const float*)d_in[3];  // [8, 1024, 2048]
    const float* Wd = (const float*)d_in[4];  // [8, 2048, 1024]
    float* out = (float*)d_out;               // final (4194304) then logits (32768)
    float* out_logits = out + (size_t)T_TOK * H_DIM;

    cudaFuncSetAttribute(mma_gemm_kernel<0>, cudaFuncAttributeMaxDynamicSharedMemorySize, SMEM_TOTAL);
    cudaFuncSetAttribute(mma_gemm_kernel<1>, cudaFuncAttributeMaxDynamicSharedMemorySize, SMEM_TOTAL);

    init_kernel<<<1, 256>>>();
    zero_out_kernel<<<(T_TOK * H_DIM / 4) / 256, 256>>>(out);
    convx_kernel<<<(T_TOK * H_DIM / 4) / 256, 256>>>(x);
    wtrans_kernel<<<dim3(I_DIM / 32, H_DIM / 64, N_EXP), 256>>>(Wg, 0);
    wtrans_kernel<<<dim3(I_DIM / 32, H_DIM / 64, N_EXP), 256>>>(Wu, 1);
    wtrans_kernel<<<dim3(H_DIM / 32, I_DIM / 64, N_EXP), 256>>>(Wd, 2);

    router_kernel<<<T_TOK / 8, 256>>>(x, gw, out_logits);
    scan_kernel<<<1, 32>>>();
    scatter_kernel<<<T_TOK / 256, 256>>>();

    // GEMM1 (fused act): [rows,1024] x W1^T -> d_mid (bf16 hi/lo)
    mma_gemm_kernel<0><<<dim3(MAXROWS / BM, (2 * I_DIM) / BN), 256, SMEM_TOTAL>>>(nullptr);
    // GEMM2 (fused combine): [rows,2048] x Wd^T -> atomicAdd into out
    mma_gemm_kernel<1><<<dim3(MAXROWS / BM, H_DIM / BN), 256, SMEM_TOTAL>>>(out);
}

// round 8
// speedup vs baseline: 1.1807x; 1.0147x over previous
#include <cuda_runtime.h>
#include <cuda_bf16.h>
#include <cstdint>
#include <math.h>

// ---------------------------------------------------------------------------
// Problem constants
#define T_TOK 4096
#define H_DIM 1024
#define I_DIM 2048
#define N_EXP 8
#define K_TOP 2
#define MAXROWS 10240   // 8192 pairs + per-expert padding to 128 => 80 tiles

// GEMM tiling
#define BM 128
#define BN 128
#define BK 32
#define ROWB 80                      // padded smem row: 32 bf16 (64B) + 16B pad
#define TILE_BYTES (128 * ROWB)      // 10240
#define STAGE_BYTES (4 * TILE_BYTES) // Ahi, Alo, Bhi, Blo
#define SMEM_TOTAL (2 * STAGE_BYTES) // 81920 -> 2 CTAs/SM

// ---------------------------------------------------------------------------
// Scratch (device globals — allocation-free; referenced ONLY from device code)
__device__ int   d_count[N_EXP];
__device__ int   d_cursor[N_EXP];
__device__ int   d_seg[N_EXP + 1];
__device__ int   d_tok[MAXROWS];
__device__ float d_roww[MAXROWS];            // combine weight per expert-row
__device__ float d_topw[T_TOK * K_TOP];
__device__ int   d_tope[T_TOK * K_TOP];

__device__ unsigned short d_xhi[(size_t)T_TOK * H_DIM];
__device__ unsigned short d_xlo[(size_t)T_TOK * H_DIM];
// W1 = gate/up interleaved at 8-col granularity: [E][4096][1024]
//   gate col j -> n' = (j>>3)*16 + (j&7);  up col j -> n' = (j>>3)*16 + 8 + (j&7)
__device__ unsigned short d_W1hi[(size_t)N_EXP * 2 * I_DIM * H_DIM];
__device__ unsigned short d_W1lo[(size_t)N_EXP * 2 * I_DIM * H_DIM];
// Wd transposed: [E][1024][2048]
__device__ unsigned short d_Wdhi[(size_t)N_EXP * H_DIM * I_DIM];
__device__ unsigned short d_Wdlo[(size_t)N_EXP * H_DIM * I_DIM];
__device__ unsigned short d_midhi[(size_t)MAXROWS * I_DIM];
__device__ unsigned short d_midlo[(size_t)MAXROWS * I_DIM];

// ---------------------------------------------------------------------------
// PTX macros (baseline PTX only: compiles for compute_103 target)
#define CP16(dst, src, sz) \
    asm volatile("cp.async.cg.shared.global [%0], [%1], 16, %2;" \
                 :: "r"(dst), "l"(src), "r"(sz) : "memory")
#define CP_COMMIT() asm volatile("cp.async.commit_group;" ::: "memory")
#define CP_WAIT0()  asm volatile("cp.async.wait_group 0;" ::: "memory")

#define LDSM_X4(r, addr) \
    asm volatile("ldmatrix.sync.aligned.m8n8.x4.shared.b16 {%0,%1,%2,%3}, [%4];" \
                 : "=r"((r)[0]), "=r"((r)[1]), "=r"((r)[2]), "=r"((r)[3]) : "r"(addr))

#define MMA_BF16(c, a, b) \
    asm volatile("mma.sync.aligned.m16n8k16.row.col.f32.bf16.bf16.f32 " \
                 "{%0,%1,%2,%3}, {%4,%5,%6,%7}, {%8,%9}, {%0,%1,%2,%3};" \
                 : "+f"((c)[0]), "+f"((c)[1]), "+f"((c)[2]), "+f"((c)[3]) \
                 : "r"((a)[0]), "r"((a)[1]), "r"((a)[2]), "r"((a)[3]), \
                   "r"((b)[0]), "r"((b)[1]))

// bf16 split helpers
__device__ __forceinline__ unsigned short bfbits(float v) {
    __nv_bfloat16 b = __float2bfloat16_rn(v);
    return *reinterpret_cast<unsigned short*>(&b);
}
__device__ __forceinline__ float bfval(unsigned short u) {
    __nv_bfloat16 b;
    *reinterpret_cast<unsigned short*>(&b) = u;
    return __bfloat162float(b);
}
__device__ __forceinline__ void split2(float v, unsigned short& h, unsigned short& l) {
    h = bfbits(v);
    l = bfbits(v - bfval(h));
}
__device__ __forceinline__ float silu_mul(float g, float u) {
    return g / (1.f + expf(-g)) * u;
}

// ---------------------------------------------------------------------------
__global__ void init_kernel() {
    int tid = threadIdx.x;
    if (tid < N_EXP) { d_count[tid] = 0; d_cursor[tid] = 0; }
    for (int i = tid; i < MAXROWS; i += blockDim.x) d_tok[i] = -1;
}

// zero the final-output region (harness poisons d_out with 0xAA)
__global__ void zero_out_kernel(float* __restrict__ out) {
    size_t i = (size_t)blockIdx.x * 256 + threadIdx.x;
    ((float4*)out)[i] = make_float4(0.f, 0.f, 0.f, 0.f);
}

// fp32 x -> bf16 hi/lo
__global__ void convx_kernel(const float* __restrict__ x) {
    size_t i = (size_t)blockIdx.x * 256 + threadIdx.x;  // float4 index
    float4 v = ((const float4*)x)[i];
    ushort4 h, l;
    split2(v.x, h.x, l.x); split2(v.y, h.y, l.y);
    split2(v.z, h.z, l.z); split2(v.w, h.w, l.w);
    ((ushort4*)d_xhi)[i] = h;
    ((ushort4*)d_xlo)[i] = l;
}

// transpose + hi/lo split with vectorized writes.
// mode 0: Wg -> W1 (interleaved even groups); 1: Wu -> W1 (odd); 2: Wd.
__global__ void wtrans_kernel(const float* __restrict__ W, int mode) {
    __shared__ float tile[64][33];
    const int Kd = (mode == 2) ? I_DIM : H_DIM;
    const int Nd = (mode == 2) ? H_DIM : I_DIM;
    const int Nb = (mode == 2) ? H_DIM : 2 * I_DIM;
    unsigned short* Thi = (mode == 2) ? d_Wdhi : d_W1hi;
    unsigned short* Tlo = (mode == 2) ? d_Wdlo : d_W1lo;

    int e = blockIdx.z;
    const float* We = W + (size_t)e * Kd * Nd;
    int nbase = blockIdx.x * 32, kbase = blockIdx.y * 64;
    int tid = threadIdx.x, tx = tid & 31, ty = tid >> 5;
#pragma unroll
    for (int r = 0; r < 64; r += 8)
        tile[r + ty][tx] = We[(size_t)(kbase + r + ty) * Nd + nbase + tx];
    __syncthreads();

    size_t ebase = (size_t)e * Nb * Kd;
#pragma unroll
    for (int task = tid; task < 512; task += 256) {
        int n = task >> 4, q = task & 15;
        int j = nbase + n;
        int np = (mode == 2) ? j
                 : (((j >> 3) << 4) | (mode == 1 ? 8 : 0) | (j & 7));
        ushort4 h, l;
        split2(tile[q * 4 + 0][n], h.x, l.x);
        split2(tile[q * 4 + 1][n], h.y, l.y);
        split2(tile[q * 4 + 2][n], h.z, l.z);
        split2(tile[q * 4 + 3][n], h.w, l.w);
        size_t o = ebase + (size_t)np * Kd + kbase + q * 4;
        *(ushort4*)(Thi + o) = h;
        *(ushort4*)(Tlo + o) = l;
    }
}

// One warp per token: logits, softmax, top-2, expert counting.
__global__ void router_kernel(const float* __restrict__ x,
                              const float* __restrict__ gw,
                              float* __restrict__ out_logits) {
    int warp = threadIdx.x >> 5, lane = threadIdx.x & 31;
    int t = blockIdx.x * 8 + warp;
    if (t >= T_TOK) return;
    const float* xr = x + (size_t)t * H_DIM;
    float acc[N_EXP];
#pragma unroll
    for (int e = 0; e < N_EXP; e++) acc[e] = 0.f;
    for (int i = lane; i < H_DIM; i += 32) {
        float xv = xr[i];
        float4 a = __ldg((const float4*)(gw + (size_t)i * N_EXP));
        float4 b = __ldg((const float4*)(gw + (size_t)i * N_EXP) + 1);
        acc[0] += xv * a.x; acc[1] += xv * a.y; acc[2] += xv * a.z; acc[3] += xv * a.w;
        acc[4] += xv * b.x; acc[5] += xv * b.y; acc[6] += xv * b.z; acc[7] += xv * b.w;
    }
#pragma unroll
    for (int off = 16; off > 0; off >>= 1)
#pragma unroll
        for (int e = 0; e < N_EXP; e++)
            acc[e] += __shfl_xor_sync(0xffffffffu, acc[e], off);
    if (lane == 0) {
#pragma unroll
        for (int e = 0; e < N_EXP; e++) out_logits[(size_t)t * N_EXP + e] = acc[e];
        float m = acc[0];
#pragma unroll
        for (int e = 1; e < N_EXP; e++) m = fmaxf(m, acc[e]);
        float p[N_EXP], s = 0.f;
#pragma unroll
        for (int e = 0; e < N_EXP; e++) { p[e] = expf(acc[e] - m); s += p[e]; }
        float inv = 1.f / s;
        int i0 = 0; float b0 = p[0];
#pragma unroll
        for (int e = 1; e < N_EXP; e++) if (p[e] > b0) { b0 = p[e]; i0 = e; }
        int i1 = -1; float b1 = -1.f;
#pragma unroll
        for (int e = 0; e < N_EXP; e++) if (e != i0 && p[e] > b1) { b1 = p[e]; i1 = e; }
        d_tope[t * 2 + 0] = i0; d_topw[t * 2 + 0] = b0 * inv;
        d_tope[t * 2 + 1] = i1; d_topw[t * 2 + 1] = b1 * inv;
        atomicAdd(&d_count[i0], 1);
        atomicAdd(&d_count[i1], 1);
    }
}

__global__ void scan_kernel() {
    if (threadIdx.x == 0) {
        int off = 0;
#pragma unroll
        for (int e = 0; e < N_EXP; e++) { d_seg[e] = off; off += (d_count[e] + 127) & ~127; }
        d_seg[N_EXP] = off;
    }
}

__global__ void scatter_kernel() {
    int t = blockIdx.x * blockDim.x + threadIdx.x;
    if (t >= T_TOK) return;
#pragma unroll
    for (int k = 0; k < K_TOP; k++) {
        int e = d_tope[t * 2 + k];
        int pos = atomicAdd(&d_cursor[e], 1);
        int row = d_seg[e] + pos;
        d_tok[row] = t;
        d_roww[row] = d_topw[t * 2 + k];
    }
}

// ---------------------------------------------------------------------------
// Grouped GEMM on mma.sync.m16n8k16 bf16, hi/lo split (3 passes), fp32 acc.
// MODE 0: A = gather(x) [K=1024], B = W1 (g/u interleaved), epilogue fuses
//         silu(g)*u -> bf16 hi/lo -> d_mid  (acc j even = gate, odd = up)
// MODE 1: A = mid [K=2048], B = Wd, epilogue fuses weighted combine:
//         out[token] += w_row * acc  (atomicAdd; exactly 2 adds/element ->
//         commutative -> deterministic)
// 128x128x32 CTA tile, 8 warps of 64x32, 2-stage cp.async, 2 CTAs/SM.
// Single __syncthreads per K-step: prefetch is issued AFTER the barrier, so
// no warp can overwrite a stage another warp is still reading.
template <int MODE>
__global__ __launch_bounds__(256, 2)
void mma_gemm_kernel(float* __restrict__ out)
{
    constexpr int Kdim = (MODE == 0) ? H_DIM : I_DIM;
    constexpr int Nb   = (MODE == 0) ? 2 * I_DIM : H_DIM;

    extern __shared__ char sm[];
    int row0 = blockIdx.x * BM;
    if (row0 >= d_seg[N_EXP]) return;

    const unsigned short* __restrict__ Ahi_g = (MODE == 0) ? d_xhi : d_midhi;
    const unsigned short* __restrict__ Alo_g = (MODE == 0) ? d_xlo : d_midlo;
    const unsigned short* __restrict__ Bhi_g = (MODE == 0) ? d_W1hi : d_Wdhi;
    const unsigned short* __restrict__ Blo_g = (MODE == 0) ? d_W1lo : d_Wdlo;

    uint32_t sbase = (uint32_t)__cvta_generic_to_shared(sm);
    int tid = threadIdx.x, lane = tid & 31, wid = tid >> 5;
    int n0 = blockIdx.y * BN;

    int e = 0;
#pragma unroll
    for (int i = 0; i < N_EXP - 1; i++) if (row0 >= d_seg[i + 1]) e = i + 1;

    // ---- per-thread load setup: 2 rows per tile (r and r+64), 16B chunk kc
    int r1 = tid >> 2, kc = tid & 3;
    const unsigned short *pAh[2], *pAl[2], *pBh[2], *pBl[2];
    uint32_t szA[2], dstoff[2];
#pragma unroll
    for (int h2 = 0; h2 < 2; h2++) {
        int r = r1 + h2 * 64;
        dstoff[h2] = (uint32_t)(r * ROWB + kc * 16);
        if (MODE == 0) {
            int tok = d_tok[row0 + r];
            if (tok >= 0) {
                pAh[h2] = Ahi_g + (size_t)tok * Kdim + kc * 8;
                pAl[h2] = Alo_g + (size_t)tok * Kdim + kc * 8;
                szA[h2] = 16;
            } else {
                pAh[h2] = Ahi_g; pAl[h2] = Alo_g; szA[h2] = 0;  // zero-fill
            }
        } else {
            pAh[h2] = Ahi_g + (size_t)(row0 + r) * Kdim + kc * 8;
            pAl[h2] = Alo_g + (size_t)(row0 + r) * Kdim + kc * 8;
            szA[h2] = 16;
        }
        size_t bo = ((size_t)e * Nb + n0 + r) * Kdim + kc * 8;
        pBh[h2] = Bhi_g + bo;
        pBl[h2] = Blo_g + bo;
    }

#define LOAD_STAGE(s, kof) do { \
    uint32_t sb_ = sbase + (s) * STAGE_BYTES; \
    _Pragma("unroll") \
    for (int h2 = 0; h2 < 2; h2++) { \
        CP16(sb_ + 0 * TILE_BYTES + dstoff[h2], pAh[h2] + (kof), szA[h2]); \
        CP16(sb_ + 1 * TILE_BYTES + dstoff[h2], pAl[h2] + (kof), szA[h2]); \
        CP16(sb_ + 2 * TILE_BYTES + dstoff[h2], pBh[h2] + (kof), 16u); \
        CP16(sb_ + 3 * TILE_BYTES + dstoff[h2], pBl[h2] + (kof), 16u); \
    } \
} while (0)

    // ---- compute setup
    int wm = (wid & 1) * 64, wn = (wid >> 1) * 32;
    uint32_t a_off = (uint32_t)((wm + (lane & 15)) * ROWB + (lane >> 4) * 16);
    uint32_t b_off = (uint32_t)((wn + (lane & 7) + ((lane >> 4) << 3)) * ROWB +
                                ((lane >> 3) & 1) * 16);

    float acc[4][4][4];
#pragma unroll
    for (int i = 0; i < 4; i++)
#pragma unroll
        for (int j = 0; j < 4; j++)
#pragma unroll
            for (int q = 0; q < 4; q++) acc[i][j][q] = 0.f;

    const int nk = Kdim / BK;
    LOAD_STAGE(0, 0);
    CP_COMMIT();

    for (int ks = 0; ks < nk; ks++) {
        int s = ks & 1;
        CP_WAIT0();          // only stage ks's group can be pending
        __syncthreads();     // everyone done computing stage s^1 (prev iter)

        if (ks + 1 < nk) {
            LOAD_STAGE(s ^ 1, (ks + 1) * BK);  // safe: issued after barrier
            CP_COMMIT();
        }

        uint32_t sb = sbase + s * STAGE_BYTES;
#pragma unroll
        for (int h = 0; h < 2; h++) {  // two k16 steps per BK=32
            // B fragments first (16 regs live), then A per-i (8 regs transient)
            uint32_t bh[4][2], bl[4][2];
#pragma unroll
            for (int jp = 0; jp < 2; jp++) {
                uint32_t tmp[4];
                uint32_t bd = sb + 2 * TILE_BYTES + b_off + jp * (16 * ROWB) + h * 32;
                LDSM_X4(tmp, bd);
                bh[jp * 2][0] = tmp[0]; bh[jp * 2][1] = tmp[1];
                bh[jp * 2 + 1][0] = tmp[2]; bh[jp * 2 + 1][1] = tmp[3];
                LDSM_X4(tmp, bd + TILE_BYTES);
                bl[jp * 2][0] = tmp[0]; bl[jp * 2][1] = tmp[1];
                bl[jp * 2 + 1][0] = tmp[2]; bl[jp * 2 + 1][1] = tmp[3];
            }
#pragma unroll
            for (int i = 0; i < 4; i++) {
                uint32_t ah[4], al[4];
                uint32_t ad = sb + a_off + i * (16 * ROWB) + h * 32;
                LDSM_X4(ah, ad);
                LDSM_X4(al, ad + TILE_BYTES);
#pragma unroll
                for (int j = 0; j < 4; j++) {
                    MMA_BF16(acc[i][j], ah, bh[j]);
                    MMA_BF16(acc[i][j], ah, bl[j]);
                    MMA_BF16(acc[i][j], al, bh[j]);
                }
            }
        }
    }

    // ---- epilogue
    int rin = lane >> 2, cin = (lane & 3) * 2;
    if (MODE == 0) {
        // acc[i][jp*2] = gate, acc[i][jp*2+1] = up for the SAME logical cols
        int midcol0 = (n0 + wn) >> 1;  // logical mid col base for this warp
#pragma unroll
        for (int i = 0; i < 4; i++)
#pragma unroll
            for (int jp = 0; jp < 2; jp++) {
                const float* g = acc[i][jp * 2];
                const float* u = acc[i][jp * 2 + 1];
                int colb = midcol0 + jp * 8 + cin;
#pragma unroll
                for (int hf = 0; hf < 2; hf++) {
                    float m0 = silu_mul(g[hf * 2 + 0], u[hf * 2 + 0]);
                    float m1 = silu_mul(g[hf * 2 + 1], u[hf * 2 + 1]);
                    ushort2 h2v, l2v;
                    split2(m0, h2v.x, l2v.x);
                    split2(m1, h2v.y, l2v.y);
                    size_t off = (size_t)(row0 + wm + i * 16 + rin + hf * 8) * I_DIM + colb;
                    *(ushort2*)(d_midhi + off) = h2v;
                    *(ushort2*)(d_midlo + off) = l2v;
                }
            }
    } else {
        // fused combine: out[token] += w_row * acc  (2 adds/element total)
        int   tokA[4], tokB[4];
        float wA[4], wB[4];
#pragma unroll
        for (int i = 0; i < 4; i++) {
            int ra = row0 + wm + i * 16 + rin;
            tokA[i] = d_tok[ra];     wA[i] = d_roww[ra];
            tokB[i] = d_tok[ra + 8]; wB[i] = d_roww[ra + 8];
        }
#pragma unroll
        for (int i = 0; i < 4; i++)
#pragma unroll
            for (int j = 0; j < 4; j++) {
                int col = n0 + wn + j * 8 + cin;
                if (tokA[i] >= 0) {
                    float* p = out + (size_t)tokA[i] * H_DIM + col;
                    atomicAdd(p,     wA[i] * acc[i][j][0]);
                    atomicAdd(p + 1, wA[i] * acc[i][j][1]);
                }
                if (tokB[i] >= 0) {
                    float* p = out + (size_t)tokB[i] * H_DIM + col;
                    atomicAdd(p,     wB[i] * acc[i][j][2]);
                    atomicAdd(p + 1, wB[i] * acc[i][j][3]);
                }
            }
    }
#undef LOAD_STAGE
}

// ---------------------------------------------------------------------------
extern "C" void kernel_launch(void* const* d_in, const int* in_sizes, int n_in,
                              void* d_out, int out_size) {
    const float* x  = (const float*)d_in[0];  // [4096, 1024]
    const float* gw = (const float*)d_in[1];  // [1024, 8]
    const float* Wg = (const float*)d_in[2];  // [8, 1024, 2048]
    const float* Wu = (const float*)d_in[3];  // [8, 1024, 2048]
    const float* Wd = (const float*)d_in[4];  // [8, 2048, 1024]
    float* out = (float*)d_out;               // final (4194304) then logits (32768)
    float* out_logits = out + (size_t)T_TOK * H_DIM;

    // One-time host resources (same enqueued work every call; no device alloc)
    static cudaStream_t s_side = nullptr;
    static cudaEvent_t ev_fork = nullptr, ev_join = nullptr;
    if (!s_side) {
        cudaStreamCreateWithFlags(&s_side, cudaStreamNonBlocking);
        cudaEventCreateWithFlags(&ev_fork, cudaEventDisableTiming);
        cudaEventCreateWithFlags(&ev_join, cudaEventDisableTiming);
        cudaFuncSetAttribute(mma_gemm_kernel<0>, cudaFuncAttributeMaxDynamicSharedMemorySize, SMEM_TOTAL);
        cudaFuncSetAttribute(mma_gemm_kernel<1>, cudaFuncAttributeMaxDynamicSharedMemorySize, SMEM_TOTAL);
    }

    // Fork: weight transposes run on a side stream, concurrent with the
    // router/dispatch chain on the main stream.
    cudaEventRecord(ev_fork, 0);
    cudaStreamWaitEvent(s_side, ev_fork, 0);
    wtrans_kernel<<<dim3(I_DIM / 32, H_DIM / 64, N_EXP), 256, 0, s_side>>>(Wg, 0);
    wtrans_kernel<<<dim3(I_DIM / 32, H_DIM / 64, N_EXP), 256, 0, s_side>>>(Wu, 1);
    wtrans_kernel<<<dim3(H_DIM / 32, I_DIM / 64, N_EXP), 256, 0, s_side>>>(Wd, 2);
    cudaEventRecord(ev_join, s_side);

    // Main stream: dispatch chain
    init_kernel<<<1, 256>>>();
    zero_out_kernel<<<(T_TOK * H_DIM / 4) / 256, 256>>>(out);
    convx_kernel<<<(T_TOK * H_DIM / 4) / 256, 256>>>(x);
    router_kernel<<<T_TOK / 8, 256>>>(x, gw, out_logits);
    scan_kernel<<<1, 32>>>();
    scatter_kernel<<<T_TOK / 256, 256>>>();

    // Join: GEMMs need the transposed weights
    cudaStreamWaitEvent(0, ev_join, 0);

    // GEMM1 (fused act): [rows,1024] x W1^T -> d_mid (bf16 hi/lo)
    mma_gemm_kernel<0><<<dim3(MAXROWS / BM, (2 * I_DIM) / BN), 256, SMEM_TOTAL>>>(nullptr);
    // GEMM2 (fused combine): [rows,2048] x Wd^T -> atomicAdd into out
    mma_gemm_kernel<1><<<dim3(MAXROWS / BM, H_DIM / BN), 256, SMEM_TOTAL>>>(out);
}